// round 1
// baseline (speedup 1.0000x reference)
#include <cuda_runtime.h>

#define BATCH  2
#define NCTX   4096
#define DMODEL 512

// Scratch (allocation-free rule: __device__ globals)
__device__ float g_K[(size_t)BATCH * NCTX * DMODEL];            // 16 MB
__device__ float g_S[(size_t)BATCH * NCTX * NCTX];              // 128 MB

__device__ __forceinline__ float neg_inf() { return __int_as_float(0xff800000); }

// ---------------------------------------------------------------------------
// Kernel 1: g_K[m][e] = sum_d x[m][d] * W[e][d]   (M=8192, N=512, K=512, NT)
// ---------------------------------------------------------------------------
__global__ __launch_bounds__(256) void proj_kernel(const float* __restrict__ x,
                                                   const float* __restrict__ W) {
    __shared__ float As[8][128];
    __shared__ float Bs[8][128];
    const int tid = threadIdx.x;
    const int tx = tid & 15, ty = tid >> 4;
    const int m0 = blockIdx.y * 128;
    const int n0 = blockIdx.x * 128;
    const int lrow = tid >> 1;
    const int lcol = (tid & 1) * 4;

    float acc[8][8] = {};
    for (int k0 = 0; k0 < DMODEL; k0 += 8) {
        float4 a = *(const float4*)(x + (size_t)(m0 + lrow) * DMODEL + k0 + lcol);
        float4 b = *(const float4*)(W + (size_t)(n0 + lrow) * DMODEL + k0 + lcol);
        As[lcol + 0][lrow] = a.x; As[lcol + 1][lrow] = a.y;
        As[lcol + 2][lrow] = a.z; As[lcol + 3][lrow] = a.w;
        Bs[lcol + 0][lrow] = b.x; Bs[lcol + 1][lrow] = b.y;
        Bs[lcol + 2][lrow] = b.z; Bs[lcol + 3][lrow] = b.w;
        __syncthreads();
        #pragma unroll
        for (int kk = 0; kk < 8; kk++) {
            float ra[8], rb[8];
            #pragma unroll
            for (int i = 0; i < 8; i++) ra[i] = As[kk][ty * 8 + i];
            #pragma unroll
            for (int j = 0; j < 8; j++) rb[j] = Bs[kk][tx * 8 + j];
            #pragma unroll
            for (int i = 0; i < 8; i++)
                #pragma unroll
                for (int j = 0; j < 8; j++) acc[i][j] += ra[i] * rb[j];
        }
        __syncthreads();
    }
    #pragma unroll
    for (int i = 0; i < 8; i++) {
        #pragma unroll
        for (int j = 0; j < 8; j += 4) {
            float4 v = make_float4(acc[i][j], acc[i][j + 1], acc[i][j + 2], acc[i][j + 3]);
            *(float4*)(g_K + (size_t)(m0 + ty * 8 + i) * DMODEL + n0 + tx * 8 + j) = v;
        }
    }
}

// ---------------------------------------------------------------------------
// Kernel 2: S[b][q][k] = sum_d x_b[q][d] * K_b[k][d]  (causal: only kt <= qt)
// ---------------------------------------------------------------------------
__global__ __launch_bounds__(256) void scores_kernel(const float* __restrict__ x) {
    const int kt = blockIdx.x, qt = blockIdx.y, b = blockIdx.z;
    if (kt > qt) return;                       // block-level causal skip
    const float* A  = x   + (size_t)b * NCTX * DMODEL;
    const float* Bm = g_K + (size_t)b * NCTX * DMODEL;
    float*       C  = g_S + (size_t)b * NCTX * NCTX;

    __shared__ float As[8][128];
    __shared__ float Bs[8][128];
    const int tid = threadIdx.x;
    const int tx = tid & 15, ty = tid >> 4;
    const int m0 = qt * 128;
    const int n0 = kt * 128;
    const int lrow = tid >> 1;
    const int lcol = (tid & 1) * 4;

    float acc[8][8] = {};
    for (int k0 = 0; k0 < DMODEL; k0 += 8) {
        float4 a = *(const float4*)(A  + (size_t)(m0 + lrow) * DMODEL + k0 + lcol);
        float4 b4= *(const float4*)(Bm + (size_t)(n0 + lrow) * DMODEL + k0 + lcol);
        As[lcol + 0][lrow] = a.x;  As[lcol + 1][lrow] = a.y;
        As[lcol + 2][lrow] = a.z;  As[lcol + 3][lrow] = a.w;
        Bs[lcol + 0][lrow] = b4.x; Bs[lcol + 1][lrow] = b4.y;
        Bs[lcol + 2][lrow] = b4.z; Bs[lcol + 3][lrow] = b4.w;
        __syncthreads();
        #pragma unroll
        for (int kk = 0; kk < 8; kk++) {
            float ra[8], rb[8];
            #pragma unroll
            for (int i = 0; i < 8; i++) ra[i] = As[kk][ty * 8 + i];
            #pragma unroll
            for (int j = 0; j < 8; j++) rb[j] = Bs[kk][tx * 8 + j];
            #pragma unroll
            for (int i = 0; i < 8; i++)
                #pragma unroll
                for (int j = 0; j < 8; j++) acc[i][j] += ra[i] * rb[j];
        }
        __syncthreads();
    }
    #pragma unroll
    for (int i = 0; i < 8; i++) {
        const int q = m0 + ty * 8 + i;
        #pragma unroll
        for (int j = 0; j < 8; j += 4) {
            const int k = n0 + tx * 8 + j;
            float4 v;
            v.x = (k + 0 <= q) ? acc[i][j + 0] : neg_inf();
            v.y = (k + 1 <= q) ? acc[i][j + 1] : neg_inf();
            v.z = (k + 2 <= q) ? acc[i][j + 2] : neg_inf();
            v.w = (k + 3 <= q) ? acc[i][j + 3] : neg_inf();
            *(float4*)(C + (size_t)q * NCTX + k) = v;
        }
    }
}

// ---------------------------------------------------------------------------
// Kernel 3: row softmax over k in [0, q]; zero-fill (q, roundup128(q+1)) so
// the output GEMM can run full 128-wide k tiles.
// ---------------------------------------------------------------------------
__global__ __launch_bounds__(256) void softmax_kernel() {
    const int q = blockIdx.x, b = blockIdx.y;
    float* row = g_S + (size_t)b * NCTX * NCTX + (size_t)q * NCTX;
    const int len = q + 1;
    const int tid = threadIdx.x;
    __shared__ float redmax[8], redsum[8];

    float m = neg_inf();
    for (int i = tid; i < len; i += 256) m = fmaxf(m, row[i]);
    #pragma unroll
    for (int o = 16; o; o >>= 1) m = fmaxf(m, __shfl_xor_sync(0xffffffffu, m, o));
    if ((tid & 31) == 0) redmax[tid >> 5] = m;
    __syncthreads();
    m = neg_inf();
    #pragma unroll
    for (int w = 0; w < 8; w++) m = fmaxf(m, redmax[w]);

    float s = 0.f;
    for (int i = tid; i < len; i += 256) s += expf(row[i] - m);
    #pragma unroll
    for (int o = 16; o; o >>= 1) s += __shfl_xor_sync(0xffffffffu, s, o);
    if ((tid & 31) == 0) redsum[tid >> 5] = s;
    __syncthreads();
    s = 0.f;
    #pragma unroll
    for (int w = 0; w < 8; w++) s += redsum[w];
    const float inv = 1.f / s;

    for (int i = tid; i < len; i += 256) row[i] = expf(row[i] - m) * inv;
    const int end = ((q >> 7) + 1) << 7;   // round up to the 128 tile boundary
    for (int i = len + tid; i < end; i += 256) row[i] = 0.f;
}

// ---------------------------------------------------------------------------
// Kernel 4: out[b][q][d] = x[b][q][d] + sum_k P[q][k] * K_b[k][d]   (NN)
// k loop truncated at the causal boundary of this q tile.
// ---------------------------------------------------------------------------
__global__ __launch_bounds__(256) void out_kernel(const float* __restrict__ x,
                                                  float* __restrict__ out) {
    const int b = blockIdx.z;
    const int n0 = blockIdx.x * 128;   // d
    const int m0 = blockIdx.y * 128;   // q
    const float* P  = g_S + (size_t)b * NCTX * NCTX;
    const float* Bm = g_K + (size_t)b * NCTX * DMODEL;
    const float* xb = x   + (size_t)b * NCTX * DMODEL;
    float*       ob = out + (size_t)b * NCTX * DMODEL;

    __shared__ float As[8][128];
    __shared__ float Bs[8][128];
    const int tid = threadIdx.x;
    const int tx = tid & 15, ty = tid >> 4;
    const int arow = tid >> 1;          // q within tile (A load)
    const int acol = (tid & 1) * 4;     // k within chunk
    const int brow = tid >> 5;          // k within chunk (B load)
    const int bcol = (tid & 31) * 4;    // d within tile

    const int kmax = m0 + 128;          // causal: k < (qt+1)*128, zero-padded above q
    float acc[8][8] = {};
    for (int k0 = 0; k0 < kmax; k0 += 8) {
        float4 a  = *(const float4*)(P  + (size_t)(m0 + arow) * NCTX   + k0 + acol);
        float4 b4 = *(const float4*)(Bm + (size_t)(k0 + brow) * DMODEL + n0 + bcol);
        As[acol + 0][arow] = a.x; As[acol + 1][arow] = a.y;
        As[acol + 2][arow] = a.z; As[acol + 3][arow] = a.w;
        *(float4*)&Bs[brow][bcol] = b4;
        __syncthreads();
        #pragma unroll
        for (int kk = 0; kk < 8; kk++) {
            float ra[8], rb[8];
            #pragma unroll
            for (int i = 0; i < 8; i++) ra[i] = As[kk][ty * 8 + i];
            #pragma unroll
            for (int j = 0; j < 8; j++) rb[j] = Bs[kk][tx * 8 + j];
            #pragma unroll
            for (int i = 0; i < 8; i++)
                #pragma unroll
                for (int j = 0; j < 8; j++) acc[i][j] += ra[i] * rb[j];
        }
        __syncthreads();
    }
    #pragma unroll
    for (int i = 0; i < 8; i++) {
        const int q = m0 + ty * 8 + i;
        #pragma unroll
        for (int j = 0; j < 8; j += 4) {
            const int d = n0 + tx * 8 + j;
            float4 xi = *(const float4*)(xb + (size_t)q * DMODEL + d);
            float4 v  = make_float4(acc[i][j] + xi.x, acc[i][j + 1] + xi.y,
                                    acc[i][j + 2] + xi.z, acc[i][j + 3] + xi.w);
            *(float4*)(ob + (size_t)q * DMODEL + d) = v;
        }
    }
}

// ---------------------------------------------------------------------------
extern "C" void kernel_launch(void* const* d_in, const int* in_sizes, int n_in,
                              void* d_out, int out_size) {
    (void)in_sizes; (void)n_in; (void)out_size;
    const float* x = (const float*)d_in[0];   // [B, NCTX, DMODEL]
    const float* W = (const float*)d_in[1];   // [DMODEL, DMODEL]
    float* out = (float*)d_out;               // [B, NCTX, DMODEL]

    // 1) K = x @ W^T  (flattened M = B*NCTX)
    proj_kernel<<<dim3(DMODEL / 128, (BATCH * NCTX) / 128), 256>>>(x, W);
    // 2) S = x @ K^T (causal lower-triangle tiles only)
    scores_kernel<<<dim3(NCTX / 128, NCTX / 128, BATCH), 256>>>(x);
    // 3) P = softmax rows (+ zero-fill to 128 boundary)
    softmax_kernel<<<dim3(NCTX, BATCH), 256>>>();
    // 4) out = x + P @ K
    out_kernel<<<dim3(DMODEL / 128, NCTX / 128, BATCH), 256>>>(x, out);
}

// round 16
// speedup vs baseline: 1.4679x; 1.4679x over previous
#include <cuda_runtime.h>
#include <cuda_bf16.h>
#include <cstdint>

#define BATCH  2
#define NCTX   4096
#define DMODEL 512
#define NM     (BATCH * NCTX)

// ---------------------------------------------------------------------------
// Scratch (__device__ globals; allocation-free rule)
// ---------------------------------------------------------------------------
__device__ float         g_K [(size_t)NM * DMODEL];                 // fp32 K
__device__ float         g_S [(size_t)BATCH * NCTX * NCTX];         // scores fp32
__device__ __nv_bfloat16 g_Kthi[(size_t)BATCH * DMODEL * NCTX];     // K^T [d][k] hi
__device__ __nv_bfloat16 g_Ktlo[(size_t)BATCH * DMODEL * NCTX];     // K^T [d][k] lo
__device__ __nv_bfloat16 g_Phi[(size_t)BATCH * NCTX * NCTX];        // softmax P hi
__device__ __nv_bfloat16 g_Plo[(size_t)BATCH * NCTX * NCTX];        // softmax P lo

__device__ __forceinline__ float neg_inf() { return __int_as_float(0xff800000); }

// ===========================================================================
// PROVEN R1 SIMT kernels (passed at rel_err 7e-8) — proj + scores
// ===========================================================================
__global__ __launch_bounds__(256) void proj_kernel(const float* __restrict__ x,
                                                   const float* __restrict__ W) {
    __shared__ float As[8][128];
    __shared__ float Bs[8][128];
    const int tid = threadIdx.x;
    const int tx = tid & 15, ty = tid >> 4;
    const int m0 = blockIdx.y * 128;
    const int n0 = blockIdx.x * 128;
    const int lrow = tid >> 1;
    const int lcol = (tid & 1) * 4;

    float acc[8][8] = {};
    for (int k0 = 0; k0 < DMODEL; k0 += 8) {
        float4 a = *(const float4*)(x + (size_t)(m0 + lrow) * DMODEL + k0 + lcol);
        float4 b = *(const float4*)(W + (size_t)(n0 + lrow) * DMODEL + k0 + lcol);
        As[lcol + 0][lrow] = a.x; As[lcol + 1][lrow] = a.y;
        As[lcol + 2][lrow] = a.z; As[lcol + 3][lrow] = a.w;
        Bs[lcol + 0][lrow] = b.x; Bs[lcol + 1][lrow] = b.y;
        Bs[lcol + 2][lrow] = b.z; Bs[lcol + 3][lrow] = b.w;
        __syncthreads();
        #pragma unroll
        for (int kk = 0; kk < 8; kk++) {
            float ra[8], rb[8];
            #pragma unroll
            for (int i = 0; i < 8; i++) ra[i] = As[kk][ty * 8 + i];
            #pragma unroll
            for (int j = 0; j < 8; j++) rb[j] = Bs[kk][tx * 8 + j];
            #pragma unroll
            for (int i = 0; i < 8; i++)
                #pragma unroll
                for (int j = 0; j < 8; j++) acc[i][j] += ra[i] * rb[j];
        }
        __syncthreads();
    }
    #pragma unroll
    for (int i = 0; i < 8; i++) {
        #pragma unroll
        for (int j = 0; j < 8; j += 4) {
            float4 v = make_float4(acc[i][j], acc[i][j + 1], acc[i][j + 2], acc[i][j + 3]);
            *(float4*)(g_K + (size_t)(m0 + ty * 8 + i) * DMODEL + n0 + tx * 8 + j) = v;
        }
    }
}

__global__ __launch_bounds__(256) void scores_kernel(const float* __restrict__ x) {
    const int kt = blockIdx.x, qt = blockIdx.y, b = blockIdx.z;
    if (kt > qt) return;
    const float* A  = x   + (size_t)b * NCTX * DMODEL;
    const float* Bm = g_K + (size_t)b * NCTX * DMODEL;
    float*       C  = g_S + (size_t)b * NCTX * NCTX;

    __shared__ float As[8][128];
    __shared__ float Bs[8][128];
    const int tid = threadIdx.x;
    const int tx = tid & 15, ty = tid >> 4;
    const int m0 = qt * 128;
    const int n0 = kt * 128;
    const int lrow = tid >> 1;
    const int lcol = (tid & 1) * 4;

    float acc[8][8] = {};
    for (int k0 = 0; k0 < DMODEL; k0 += 8) {
        float4 a = *(const float4*)(A  + (size_t)(m0 + lrow) * DMODEL + k0 + lcol);
        float4 b4= *(const float4*)(Bm + (size_t)(n0 + lrow) * DMODEL + k0 + lcol);
        As[lcol + 0][lrow] = a.x;  As[lcol + 1][lrow] = a.y;
        As[lcol + 2][lrow] = a.z;  As[lcol + 3][lrow] = a.w;
        Bs[lcol + 0][lrow] = b4.x; Bs[lcol + 1][lrow] = b4.y;
        Bs[lcol + 2][lrow] = b4.z; Bs[lcol + 3][lrow] = b4.w;
        __syncthreads();
        #pragma unroll
        for (int kk = 0; kk < 8; kk++) {
            float ra[8], rb[8];
            #pragma unroll
            for (int i = 0; i < 8; i++) ra[i] = As[kk][ty * 8 + i];
            #pragma unroll
            for (int j = 0; j < 8; j++) rb[j] = Bs[kk][tx * 8 + j];
            #pragma unroll
            for (int i = 0; i < 8; i++)
                #pragma unroll
                for (int j = 0; j < 8; j++) acc[i][j] += ra[i] * rb[j];
        }
        __syncthreads();
    }
    #pragma unroll
    for (int i = 0; i < 8; i++) {
        const int q = m0 + ty * 8 + i;
        #pragma unroll
        for (int j = 0; j < 8; j += 4) {
            const int k = n0 + tx * 8 + j;
            float4 v;
            v.x = (k + 0 <= q) ? acc[i][j + 0] : neg_inf();
            v.y = (k + 1 <= q) ? acc[i][j + 1] : neg_inf();
            v.z = (k + 2 <= q) ? acc[i][j + 2] : neg_inf();
            v.w = (k + 3 <= q) ? acc[i][j + 3] : neg_inf();
            *(float4*)(C + (size_t)q * NCTX + k) = v;
        }
    }
}

// ===========================================================================
// HMMA machinery (under test) — used ONLY for out = x + P @ K
// ===========================================================================
__device__ __forceinline__ uint32_t smem_u32(const void* p) {
    uint32_t a;
    asm("{ .reg .u64 t; cvta.to.shared.u64 t, %1; cvt.u32.u64 %0, t; }" : "=r"(a) : "l"(p));
    return a;
}

__device__ __forceinline__ void cpasync16(uint32_t dst, const void* src) {
    asm volatile("cp.async.ca.shared.global [%0], [%1], 16;" :: "r"(dst), "l"(src));
}

__device__ __forceinline__ uint32_t lds32(uint32_t addr) {
    uint32_t v;
    asm volatile("ld.shared.b32 %0, [%1];" : "=r"(v) : "r"(addr));
    return v;
}

__device__ __forceinline__ void mma16816(float* d, const uint32_t* a, const uint32_t* b) {
    asm volatile("mma.sync.aligned.m16n8k16.row.col.f32.bf16.bf16.f32 "
                 "{%0,%1,%2,%3}, {%4,%5,%6,%7}, {%8,%9}, {%0,%1,%2,%3};"
                 : "+f"(d[0]), "+f"(d[1]), "+f"(d[2]), "+f"(d[3])
                 : "r"(a[0]), "r"(a[1]), "r"(a[2]), "r"(a[3]), "r"(b[0]), "r"(b[1]));
}

#define TILE_B   10240
#define BUF_B    20480
#define SMEM_GEMM (2 * BUF_B)

__device__ __forceinline__ void mma_compute(float (&acc)[4][4][4],
                                            uint32_t Ab, uint32_t Bb,
                                            int lane, int warp_m, int warp_n) {
    const int g = lane >> 2;
    const int t = lane & 3;
    #pragma unroll
    for (int kk = 0; kk < 2; kk++) {
        const int kb = kk * 32;
        uint32_t a[4][4];
        #pragma unroll
        for (int mt = 0; mt < 4; mt++) {
            uint32_t base = Ab + (uint32_t)(warp_m * 64 + mt * 16 + g) * 80 + kb + t * 4;
            a[mt][0] = lds32(base);
            a[mt][1] = lds32(base + 8 * 80);
            a[mt][2] = lds32(base + 16);
            a[mt][3] = lds32(base + 8 * 80 + 16);
        }
        uint32_t b[4][2];
        #pragma unroll
        for (int nt = 0; nt < 4; nt++) {
            uint32_t base = Bb + (uint32_t)(warp_n * 32 + nt * 8 + g) * 80 + kb + t * 4;
            b[nt][0] = lds32(base);
            b[nt][1] = lds32(base + 16);
        }
        #pragma unroll
        for (int mt = 0; mt < 4; mt++)
            #pragma unroll
            for (int nt = 0; nt < 4; nt++)
                mma16816(acc[mt][nt], a[mt], b[nt]);
    }
}

__device__ __forceinline__ void run_gemm(float (&acc)[4][4][4],
                                         const __nv_bfloat16* Ahi, const __nv_bfloat16* Alo,
                                         const __nv_bfloat16* Bhi, const __nv_bfloat16* Blo,
                                         int strideA, int strideB, int ncp, uint32_t sbase) {
    const int tid = threadIdx.x;
    const int lane = tid & 31, wid = tid >> 5;
    const int warp_m = wid >> 2, warp_n = wid & 3;
    const int lr = tid >> 2, lc = tid & 3;
    const int total = 3 * ncp;

    auto load = [&](int c, int bsel) {
        int p = c / ncp;
        const __nv_bfloat16* A = (p == 1) ? Alo : Ahi;
        const __nv_bfloat16* B = (p == 2) ? Blo : Bhi;
        int k0 = (c % ncp) * 32 + lc * 8;
        uint32_t Ab = sbase + bsel * BUF_B;
        uint32_t Bb = Ab + TILE_B;
        #pragma unroll
        for (int i = 0; i < 2; i++) {
            int r = lr + i * 64;
            cpasync16(Ab + r * 80 + lc * 16, A + (size_t)r * strideA + k0);
            cpasync16(Bb + r * 80 + lc * 16, B + (size_t)r * strideB + k0);
        }
        asm volatile("cp.async.commit_group;" ::: "memory");
    };

    load(0, 0);
    for (int c = 0; c < total; c++) {
        if (c + 1 < total) {
            load(c + 1, (c + 1) & 1);
            asm volatile("cp.async.wait_group 1;" ::: "memory");
        } else {
            asm volatile("cp.async.wait_group 0;" ::: "memory");
        }
        __syncthreads();
        uint32_t Ab = sbase + (c & 1) * BUF_B;
        mma_compute(acc, Ab, Ab + TILE_B, lane, warp_m, warp_n);
        __syncthreads();
    }
}

__device__ __forceinline__ uint32_t pack_bf16(__nv_bfloat16 a, __nv_bfloat16 b) {
    return ((uint32_t)__bfloat16_as_ushort(b) << 16) | __bfloat16_as_ushort(a);
}

// ---------------------------------------------------------------------------
// [k][d] fp32 -> [d][k] bf16 hi/lo, 64x64 tiles
// ---------------------------------------------------------------------------
__global__ __launch_bounds__(256) void transpose_split_kernel() {
    __shared__ float t[64][65];
    const int d0 = blockIdx.x * 64, k0 = blockIdx.y * 64, b = blockIdx.z;
    const float* src = g_K + (size_t)b * NCTX * DMODEL;
    #pragma unroll
    for (int i = 0; i < 16; i++) {
        int idx = threadIdx.x + 256 * i;
        int r = idx >> 6, c = idx & 63;
        t[r][c] = src[(size_t)(k0 + r) * DMODEL + d0 + c];
    }
    __syncthreads();
    __nv_bfloat16* dh = g_Kthi + (size_t)b * DMODEL * NCTX;
    __nv_bfloat16* dl = g_Ktlo + (size_t)b * DMODEL * NCTX;
    #pragma unroll
    for (int i = 0; i < 16; i++) {
        int idx = threadIdx.x + 256 * i;
        int r = idx >> 6, c = idx & 63;
        float v = t[c][r];
        __nv_bfloat16 h = __float2bfloat16(v);
        __nv_bfloat16 l = __float2bfloat16(v - __bfloat162float(h));
        dh[(size_t)(d0 + r) * NCTX + k0 + c] = h;
        dl[(size_t)(d0 + r) * NCTX + k0 + c] = l;
    }
}

// ---------------------------------------------------------------------------
// Softmax rows (register-resident); emits bf16 hi/lo P + zero-pad to 128
// ---------------------------------------------------------------------------
__global__ __launch_bounds__(256) void softmax_kernel() {
    const int q = blockIdx.x, b = blockIdx.y;
    const float* row = g_S + (size_t)b * NCTX * NCTX + (size_t)q * NCTX;
    __nv_bfloat16* ph = g_Phi + (size_t)b * NCTX * NCTX + (size_t)q * NCTX;
    __nv_bfloat16* pl = g_Plo + (size_t)b * NCTX * NCTX + (size_t)q * NCTX;
    const int len = q + 1;
    const int tid = threadIdx.x;
    __shared__ float redm[8], reds[8];

    float v[16];
    float m = neg_inf();
    #pragma unroll
    for (int j = 0; j < 16; j++) {
        int i = tid + j * 256;
        v[j] = (i < len) ? row[i] : neg_inf();
        m = fmaxf(m, v[j]);
    }
    #pragma unroll
    for (int o = 16; o; o >>= 1) m = fmaxf(m, __shfl_xor_sync(0xffffffffu, m, o));
    if ((tid & 31) == 0) redm[tid >> 5] = m;
    __syncthreads();
    m = redm[0];
    #pragma unroll
    for (int w = 1; w < 8; w++) m = fmaxf(m, redm[w]);

    float s = 0.f;
    #pragma unroll
    for (int j = 0; j < 16; j++) { float e = expf(v[j] - m); v[j] = e; s += e; }
    #pragma unroll
    for (int o = 16; o; o >>= 1) s += __shfl_xor_sync(0xffffffffu, s, o);
    if ((tid & 31) == 0) reds[tid >> 5] = s;
    __syncthreads();
    s = 0.f;
    #pragma unroll
    for (int w = 0; w < 8; w++) s += reds[w];
    const float inv = 1.f / s;

    #pragma unroll
    for (int j = 0; j < 16; j++) {
        int i = tid + j * 256;
        if (i < len) {
            float p = v[j] * inv;
            __nv_bfloat16 h = __float2bfloat16(p);
            __nv_bfloat16 l = __float2bfloat16(p - __bfloat162float(h));
            ph[i] = h; pl[i] = l;
        }
    }
    const int end = ((q >> 7) + 1) << 7;
    for (int i = len + tid; i < end; i += 256) {
        ph[i] = __float2bfloat16(0.f);
        pl[i] = __float2bfloat16(0.f);
    }
}

// ---------------------------------------------------------------------------
// HMMA GEMM: out = x + P @ K   (k truncated at causal boundary)
// ---------------------------------------------------------------------------
__global__ __launch_bounds__(256) void out_mma(const float* __restrict__ x,
                                               float* __restrict__ out) {
    const int dt = blockIdx.x, qt = blockIdx.y, b = blockIdx.z;
    extern __shared__ char smem[];
    const uint32_t sbase = smem_u32(smem);
    const size_t poff = (size_t)b * NCTX * NCTX + (size_t)qt * 128 * NCTX;
    const size_t toff = (size_t)b * DMODEL * NCTX + (size_t)dt * 128 * NCTX;
    float acc[4][4][4] = {};
    run_gemm(acc, g_Phi + poff, g_Plo + poff, g_Kthi + toff, g_Ktlo + toff,
             NCTX, NCTX, (qt + 1) * 4, sbase);

    const float* xb = x + (size_t)b * NCTX * DMODEL;
    float* ob = out + (size_t)b * NCTX * DMODEL;
    const int lane = threadIdx.x & 31, wid = threadIdx.x >> 5;
    const int warp_m = wid >> 2, warp_n = wid & 3;
    const int mi = lane >> 2, ni = (lane & 3) * 2;
    #pragma unroll
    for (int mt = 0; mt < 4; mt++)
        #pragma unroll
        for (int nt = 0; nt < 4; nt++)
            #pragma unroll
            for (int h = 0; h < 2; h++) {
                int q = qt * 128 + warp_m * 64 + mt * 16 + mi + h * 8;
                int d = dt * 128 + warp_n * 32 + nt * 8 + ni;
                size_t off = (size_t)q * DMODEL + d;
                float2 xi = *(const float2*)(xb + off);
                *(float2*)(ob + off) = make_float2(acc[mt][nt][2 * h] + xi.x,
                                                   acc[mt][nt][2 * h + 1] + xi.y);
            }
}

// ---------------------------------------------------------------------------
extern "C" void kernel_launch(void* const* d_in, const int* in_sizes, int n_in,
                              void* d_out, int out_size) {
    (void)in_sizes; (void)n_in; (void)out_size;
    const float* x = (const float*)d_in[0];
    const float* W = (const float*)d_in[1];
    float* out = (float*)d_out;

    // 1) K = x @ W^T  (PROVEN SIMT)
    proj_kernel<<<dim3(DMODEL / 128, NM / 128), 256>>>(x, W);
    // 2) K^T hi/lo split for the HMMA out GEMM
    transpose_split_kernel<<<dim3(DMODEL / 64, NCTX / 64, BATCH), 256>>>();
    // 3) S = x @ K^T causal (PROVEN SIMT)
    scores_kernel<<<dim3(NCTX / 128, NCTX / 128, BATCH), 256>>>(x);
    // 4) P = softmax(S) -> bf16 hi/lo + pad
    softmax_kernel<<<dim3(NCTX, BATCH), 256>>>();
    // 5) out = x + P @ K   (HMMA under test)
    out_mma<<<dim3(DMODEL / 128, NCTX / 128, BATCH), 256, SMEM_GEMM>>>(x, out);
}